// round 1
// baseline (speedup 1.0000x reference)
#include <cuda_runtime.h>
#include <math.h>

#define FRAMES 2048
#define BEPS 1e-5f

// ---------------- scratch (global device arrays; no allocation) ----------------
__device__ __align__(16) float g_y1[FRAMES * 16 * 144];   // [2048,16,12,12]
__device__ float g_c[FRAMES];                              // c, [32*64]
__device__ int   g_p[32];
__device__ int   g_chain[6][32];
__device__ int   g_chain_len[6];

__device__ __forceinline__ float fast_sigmoid(float x) {
    return 1.0f / (1.0f + __expf(-x));
}
__device__ __forceinline__ float fast_tanh(float x) {
    return 1.0f - 2.0f / (1.0f + __expf(2.0f * x));
}
__device__ __forceinline__ float acc4(float acc, float4 a, float4 b) {
    acc = fmaf(a.x, b.x, acc);
    acc = fmaf(a.y, b.y, acc);
    acc = fmaf(a.z, b.z, acc);
    acc = fmaf(a.w, b.w, acc);
    return acc;
}

// ---------------- Kernel A: conv1 + bias + BN + ReLU + 3x3/3 maxpool ----------
// grid: (2048 frames, 12 pooled rows), block: 96 threads.
// Each block: loads 3x12x144 floats (one pooled-row band) into SMEM,
// thread (px, chp) computes 2 channels for pooled col px.
__global__ void __launch_bounds__(96) conv1_kernel(
    const float* __restrict__ x,        // [2048,3,144,144]
    const float* __restrict__ w,        // [16,3,4,4]
    const float* __restrict__ bias,     // [16]
    const float* __restrict__ bg, const float* __restrict__ bb,
    const float* __restrict__ bm, const float* __restrict__ bv)
{
    __shared__ float4 smem[1296];       // 3 * 12 * 36 float4 = 20736 B
    const int f  = blockIdx.x;
    const int py = blockIdx.y;
    const int tid = threadIdx.x;

    const float4* xin = (const float4*)x;
    const long base = (long)f * 15552 + (long)py * 432;   // f4 units
    for (int i = tid; i < 1296; i += 96) {
        int ic  = i / 432;
        int rem = i - ic * 432;                 // r*36 + q
        smem[i] = xin[base + (long)ic * 5184 + rem];
    }
    __syncthreads();

    const int chp = tid & 7;       // 0..7
    const int px  = tid >> 3;      // 0..11
    const int ch0 = chp * 2, ch1 = ch0 + 1;

    // weights in registers: 12 float4 per channel
    float4 w0[12], w1[12];
    const float4* wf4 = (const float4*)w;
    #pragma unroll
    for (int i = 0; i < 12; i++) { w0[i] = wf4[ch0 * 12 + i]; w1[i] = wf4[ch1 * 12 + i]; }

    const float s0 = bg[ch0] * rsqrtf(bv[ch0] + BEPS);
    const float s1 = bg[ch1] * rsqrtf(bv[ch1] + BEPS);
    const float t0 = bb[ch0] - bm[ch0] * s0;
    const float t1 = bb[ch1] - bm[ch1] * s1;
    const float b0 = bias[ch0], b1 = bias[ch1];

    float m0 = -1e30f, m1 = -1e30f;
    #pragma unroll
    for (int sy = 0; sy < 3; sy++) {
        #pragma unroll
        for (int sx = 0; sx < 3; sx++) {
            float a0 = b0, a1 = b1;
            #pragma unroll
            for (int ic = 0; ic < 3; ic++) {
                #pragma unroll
                for (int ky = 0; ky < 4; ky++) {
                    float4 v = smem[(ic * 12 + sy * 4 + ky) * 36 + px * 3 + sx];
                    a0 = acc4(a0, v, w0[ic * 4 + ky]);
                    a1 = acc4(a1, v, w1[ic * 4 + ky]);
                }
            }
            m0 = fmaxf(m0, fmaxf(fmaf(a0, s0, t0), 0.0f));
            m1 = fmaxf(m1, fmaxf(fmaf(a1, s1, t1), 0.0f));
        }
    }
    g_y1[((f * 16 + ch0) * 12 + py) * 12 + px] = m0;
    g_y1[((f * 16 + ch1) * 12 + py) * 12 + px] = m1;
}

// ---------------- Kernel B: conv2 + bias + BN + ReLU + 3x3 maxpool -> scalar --
// one warp per frame; block = 256 threads = 8 frames.
__global__ void __launch_bounds__(256) conv2_kernel(
    const float* __restrict__ w2,       // [1,16,4,4]
    const float* __restrict__ b2p,      // [1]
    const float* __restrict__ bg, const float* __restrict__ bb,
    const float* __restrict__ bm, const float* __restrict__ bv)
{
    const int f = blockIdx.x * 8 + (threadIdx.x >> 5);
    const int lane = threadIdx.x & 31;
    const int ch = lane & 15, half = lane >> 4;

    const float4* wf4 = (const float4*)w2;              // 16 ch * 4 f4 rows
    const float4 wa = wf4[ch * 4 + half * 2 + 0];
    const float4 wb = wf4[ch * 4 + half * 2 + 1];

    const float scale = bg[0] * rsqrtf(bv[0] + BEPS);
    const float shift = bb[0] - bm[0] * scale;
    const float cb = b2p[0];

    const float4* y4 = (const float4*)g_y1;
    const long cbase = ((long)f * 16 + ch) * 36;        // 12x12 floats = 36 f4 per ch

    float best = -1e30f;
    #pragma unroll
    for (int sy = 0; sy < 3; sy++) {
        #pragma unroll
        for (int sx = 0; sx < 3; sx++) {
            int ky0 = half * 2;
            float4 va = y4[cbase + (sy * 4 + ky0) * 3 + sx];
            float4 vb = y4[cbase + (sy * 4 + ky0 + 1) * 3 + sx];
            float acc = acc4(acc4(0.0f, va, wa), vb, wb);
            #pragma unroll
            for (int off = 16; off; off >>= 1)
                acc += __shfl_xor_sync(0xffffffffu, acc, off);
            float val = fmaxf(fmaf(acc + cb, scale, shift), 0.0f);
            best = fmaxf(best, val);
        }
    }
    if (lane == 0) g_c[f] = best;
}

// ---------------- Kernel C: gating MLP + argmax + chain build ----------------
// 1 block, 32 threads (thread = batch sample).
__global__ void __launch_bounds__(32) gate_kernel(
    const float* __restrict__ w1, const float* __restrict__ b1,
    const float* __restrict__ w2, const float* __restrict__ b2,
    const float* __restrict__ w3, const float* __restrict__ b3)
{
    __shared__ float sc[32][65];
    const int tid = threadIdx.x;
    for (int i = tid; i < 2048; i += 32) sc[i >> 6][i & 63] = g_c[i];
    __syncwarp();

    float h1[32];
    #pragma unroll
    for (int j = 0; j < 32; j++) {
        float acc = b1[j];
        #pragma unroll 8
        for (int t = 0; t < 64; t++) acc = fmaf(sc[tid][t], w1[j * 64 + t], acc);
        h1[j] = fast_tanh(acc);
    }
    float h2[32];
    #pragma unroll
    for (int j = 0; j < 32; j++) {
        float acc = b2[j];
        #pragma unroll
        for (int t = 0; t < 32; t++) acc = fmaf(h1[t], w2[j * 32 + t], acc);
        h2[j] = fast_tanh(acc);
    }
    float bestv = -1e30f; int besti = 0;
    #pragma unroll
    for (int a = 0; a < 6; a++) {
        float acc = b3[a];
        #pragma unroll
        for (int t = 0; t < 32; t++) acc = fmaf(h2[t], w3[a * 32 + t], acc);
        if (acc > bestv) { bestv = acc; besti = a; }
    }
    g_p[tid] = besti;
    __syncwarp();

    if (tid == 0) {
        int cnt[6] = {0, 0, 0, 0, 0, 0};
        for (int b = 0; b < 32; b++) {
            int e = g_p[b];
            g_chain[e][cnt[e]++] = b;
        }
        for (int e = 0; e < 6; e++) g_chain_len[e] = cnt[e];
    }
}

// ---------------- Kernel D: per-expert LSTM chains + output head -------------
// 6 blocks (one per expert), 32 threads (lane = hidden unit).
__global__ void __launch_bounds__(32) lstm_kernel(
    const float* __restrict__ wih,   // [6,128,1]
    const float* __restrict__ whh,   // [6,128,32]
    const float* __restrict__ bih,   // [6,128]
    const float* __restrict__ bhh,   // [6,128]
    const float* __restrict__ hn0,   // [6,32]
    const float* __restrict__ outw,  // [6(=lenA),64]
    const float* __restrict__ outb,  // [6]
    float* __restrict__ out)         // [32,6]
{
    const int e = blockIdx.x;
    const int k = threadIdx.x;
    const int len = g_chain_len[e];
    if (len == 0) return;

    // register-resident recurrent weights: rows k, 32+k, 64+k, 96+k
    float4 Wi[8], Wf[8], Wg[8], Wo[8];
    const float4* b4 = (const float4*)(whh + (long)e * 4096);
    #pragma unroll
    for (int i = 0; i < 8; i++) {
        Wi[i] = b4[(0  + k) * 8 + i];
        Wf[i] = b4[(32 + k) * 8 + i];
        Wg[i] = b4[(64 + k) * 8 + i];
        Wo[i] = b4[(96 + k) * 8 + i];
    }
    const float wii = wih[e * 128 + 0  + k];
    const float wif = wih[e * 128 + 32 + k];
    const float wig = wih[e * 128 + 64 + k];
    const float wio = wih[e * 128 + 96 + k];
    const float bi_ = bih[e * 128 + 0  + k] + bhh[e * 128 + 0  + k];
    const float bf_ = bih[e * 128 + 32 + k] + bhh[e * 128 + 32 + k];
    const float bg_ = bih[e * 128 + 64 + k] + bhh[e * 128 + 64 + k];
    const float bo_ = bih[e * 128 + 96 + k] + bhh[e * 128 + 96 + k];

    float h = hn0[e * 32 + k];

    __shared__ float sh[32];
    __shared__ float scx[64];
    __shared__ float sr[64];

    for (int s = 0; s < len; s++) {
        const int b = g_chain[e][s];
        scx[k]      = g_c[b * 64 + k];
        scx[k + 32] = g_c[b * 64 + 32 + k];
        sh[k] = h;
        float cst = 0.0f;
        __syncwarp();

        for (int t = 0; t < 64; t++) {
            const float xt = scx[t];
            float ai = fmaf(wii, xt, bi_);
            float af = fmaf(wif, xt, bf_);
            float ag = fmaf(wig, xt, bg_);
            float ao = fmaf(wio, xt, bo_);
            #pragma unroll
            for (int q = 0; q < 8; q++) {
                float hm0 = sh[4 * q + 0];
                float hm1 = sh[4 * q + 1];
                float hm2 = sh[4 * q + 2];
                float hm3 = sh[4 * q + 3];
                float4 wi = Wi[q], wf = Wf[q], wg = Wg[q], wo = Wo[q];
                ai = fmaf(wi.x, hm0, ai); af = fmaf(wf.x, hm0, af);
                ag = fmaf(wg.x, hm0, ag); ao = fmaf(wo.x, hm0, ao);
                ai = fmaf(wi.y, hm1, ai); af = fmaf(wf.y, hm1, af);
                ag = fmaf(wg.y, hm1, ag); ao = fmaf(wo.y, hm1, ao);
                ai = fmaf(wi.z, hm2, ai); af = fmaf(wf.z, hm2, af);
                ag = fmaf(wg.z, hm2, ag); ao = fmaf(wo.z, hm2, ao);
                ai = fmaf(wi.w, hm3, ai); af = fmaf(wf.w, hm3, af);
                ag = fmaf(wg.w, hm3, ag); ao = fmaf(wo.w, hm3, ao);
            }
            const float ig = fast_sigmoid(ai);
            const float fg = fast_sigmoid(af);
            const float gg = fast_tanh(ag);
            const float og = fast_sigmoid(ao);
            cst = fmaf(fg, cst, ig * gg);
            h = og * fast_tanh(cst);
            __syncwarp();                 // all lanes done reading old sh
            sh[k] = h;
            if (k == 31) sr[t] = h;
            __syncwarp();                 // new sh/sr visible
        }

        if (k < 6) {
            float acc = outb[k];
            #pragma unroll 8
            for (int t = 0; t < 64; t++) acc = fmaf(sr[t], outw[k * 64 + t], acc);
            out[b * 6 + k] = acc;
        }
        __syncwarp();
    }
}

// ---------------- launch ----------------
extern "C" void kernel_launch(void* const* d_in, const int* in_sizes, int n_in,
                              void* d_out, int out_size)
{
    const float* x       = (const float*)d_in[0];
    const float* conv1_w = (const float*)d_in[1];
    const float* conv1_b = (const float*)d_in[2];
    const float* bn1_g   = (const float*)d_in[3];
    const float* bn1_b   = (const float*)d_in[4];
    const float* bn1_m   = (const float*)d_in[5];
    const float* bn1_v   = (const float*)d_in[6];
    const float* conv2_w = (const float*)d_in[7];
    const float* conv2_b = (const float*)d_in[8];
    const float* bn2_g   = (const float*)d_in[9];
    const float* bn2_b   = (const float*)d_in[10];
    const float* bn2_m   = (const float*)d_in[11];
    const float* bn2_v   = (const float*)d_in[12];
    const float* pre_w1  = (const float*)d_in[13];
    const float* pre_b1  = (const float*)d_in[14];
    const float* pre_w2  = (const float*)d_in[15];
    const float* pre_b2  = (const float*)d_in[16];
    const float* pre_w3  = (const float*)d_in[17];
    const float* pre_b3  = (const float*)d_in[18];
    const float* lstm_wih = (const float*)d_in[19];
    const float* lstm_whh = (const float*)d_in[20];
    const float* lstm_bih = (const float*)d_in[21];
    const float* lstm_bhh = (const float*)d_in[22];
    const float* hn0     = (const float*)d_in[23];
    const float* out_w   = (const float*)d_in[24];
    const float* out_b   = (const float*)d_in[25];
    float* out = (float*)d_out;

    dim3 gridA(FRAMES, 12);
    conv1_kernel<<<gridA, 96>>>(x, conv1_w, conv1_b, bn1_g, bn1_b, bn1_m, bn1_v);
    conv2_kernel<<<FRAMES / 8, 256>>>(conv2_w, conv2_b, bn2_g, bn2_b, bn2_m, bn2_v);
    gate_kernel<<<1, 32>>>(pre_w1, pre_b1, pre_w2, pre_b2, pre_w3, pre_b3);
    lstm_kernel<<<6, 32>>>(lstm_wih, lstm_whh, lstm_bih, lstm_bhh, hn0, out_w, out_b, out);
}

// round 2
// speedup vs baseline: 1.3590x; 1.3590x over previous
#include <cuda_runtime.h>
#include <math.h>

#define FRAMES 2048
#define BEPS 1e-5f

typedef unsigned long long ull;

// ---------------- scratch (global device arrays; no allocation) ----------------
__device__ __align__(16) float g_y1[FRAMES * 16 * 144];   // [2048,16,12,12]
__device__ float g_c[FRAMES];                              // c, [32*64]
__device__ int   g_p[32];
__device__ int   g_chain[6][32];
__device__ int   g_chain_len[6];

__device__ __forceinline__ float fast_tanh(float x) {
    return 1.0f - 2.0f / (1.0f + __expf(2.0f * x));
}
__device__ __forceinline__ float tanhap(float x) {
    float y;
    asm("tanh.approx.f32 %0, %1;" : "=f"(y) : "f"(x));
    return y;
}
__device__ __forceinline__ float sigap(float x) {
    return fmaf(0.5f, tanhap(0.5f * x), 0.5f);
}
__device__ __forceinline__ ull fma2(ull a, ull b, ull c) {
    ull d;
    asm("fma.rn.f32x2 %0, %1, %2, %3;" : "=l"(d) : "l"(a), "l"(b), "l"(c));
    return d;
}
__device__ __forceinline__ ull add2(ull a, ull b) {
    ull d;
    asm("add.rn.f32x2 %0, %1, %2;" : "=l"(d) : "l"(a), "l"(b));
    return d;
}
__device__ __forceinline__ float lo2(ull a) { return __uint_as_float((unsigned)(a & 0xffffffffu)); }
__device__ __forceinline__ float hi2(ull a) { return __uint_as_float((unsigned)(a >> 32)); }
__device__ __forceinline__ float acc4(float acc, float4 a, float4 b) {
    acc = fmaf(a.x, b.x, acc);
    acc = fmaf(a.y, b.y, acc);
    acc = fmaf(a.z, b.z, acc);
    acc = fmaf(a.w, b.w, acc);
    return acc;
}

// ---------------- Kernel A: conv1 + bias + BN + ReLU + 3x3/3 maxpool ----------
__global__ void __launch_bounds__(96) conv1_kernel(
    const float* __restrict__ x,        // [2048,3,144,144]
    const float* __restrict__ w,        // [16,3,4,4]
    const float* __restrict__ bias,     // [16]
    const float* __restrict__ bg, const float* __restrict__ bb,
    const float* __restrict__ bm, const float* __restrict__ bv)
{
    __shared__ float4 smem[1296];       // 3 * 12 * 36 float4 = 20736 B
    const int f  = blockIdx.x;
    const int py = blockIdx.y;
    const int tid = threadIdx.x;

    const float4* xin = (const float4*)x;
    const long base = (long)f * 15552 + (long)py * 432;   // f4 units
    for (int i = tid; i < 1296; i += 96) {
        int ic  = i / 432;
        int rem = i - ic * 432;                 // r*36 + q
        smem[i] = xin[base + (long)ic * 5184 + rem];
    }
    __syncthreads();

    const int chp = tid & 7;       // 0..7
    const int px  = tid >> 3;      // 0..11
    const int ch0 = chp * 2, ch1 = ch0 + 1;

    float4 w0[12], w1[12];
    const float4* wf4 = (const float4*)w;
    #pragma unroll
    for (int i = 0; i < 12; i++) { w0[i] = wf4[ch0 * 12 + i]; w1[i] = wf4[ch1 * 12 + i]; }

    const float s0 = bg[ch0] * rsqrtf(bv[ch0] + BEPS);
    const float s1 = bg[ch1] * rsqrtf(bv[ch1] + BEPS);
    const float t0 = bb[ch0] - bm[ch0] * s0;
    const float t1 = bb[ch1] - bm[ch1] * s1;
    const float b0 = bias[ch0], b1 = bias[ch1];

    float m0 = -1e30f, m1 = -1e30f;
    #pragma unroll
    for (int sy = 0; sy < 3; sy++) {
        #pragma unroll
        for (int sx = 0; sx < 3; sx++) {
            float a0 = b0, a1 = b1;
            #pragma unroll
            for (int ic = 0; ic < 3; ic++) {
                #pragma unroll
                for (int ky = 0; ky < 4; ky++) {
                    float4 v = smem[(ic * 12 + sy * 4 + ky) * 36 + px * 3 + sx];
                    a0 = acc4(a0, v, w0[ic * 4 + ky]);
                    a1 = acc4(a1, v, w1[ic * 4 + ky]);
                }
            }
            m0 = fmaxf(m0, fmaxf(fmaf(a0, s0, t0), 0.0f));
            m1 = fmaxf(m1, fmaxf(fmaf(a1, s1, t1), 0.0f));
        }
    }
    g_y1[((f * 16 + ch0) * 12 + py) * 12 + px] = m0;
    g_y1[((f * 16 + ch1) * 12 + py) * 12 + px] = m1;
}

// ---------------- Kernel B: conv2 + bias + BN + ReLU + 3x3 maxpool -> scalar --
__global__ void __launch_bounds__(256) conv2_kernel(
    const float* __restrict__ w2, const float* __restrict__ b2p,
    const float* __restrict__ bg, const float* __restrict__ bb,
    const float* __restrict__ bm, const float* __restrict__ bv)
{
    const int f = blockIdx.x * 8 + (threadIdx.x >> 5);
    const int lane = threadIdx.x & 31;
    const int ch = lane & 15, half = lane >> 4;

    const float4* wf4 = (const float4*)w2;
    const float4 wa = wf4[ch * 4 + half * 2 + 0];
    const float4 wb = wf4[ch * 4 + half * 2 + 1];

    const float scale = bg[0] * rsqrtf(bv[0] + BEPS);
    const float shift = bb[0] - bm[0] * scale;
    const float cb = b2p[0];

    const float4* y4 = (const float4*)g_y1;
    const long cbase = ((long)f * 16 + ch) * 36;

    float best = -1e30f;
    #pragma unroll
    for (int sy = 0; sy < 3; sy++) {
        #pragma unroll
        for (int sx = 0; sx < 3; sx++) {
            int ky0 = half * 2;
            float4 va = y4[cbase + (sy * 4 + ky0) * 3 + sx];
            float4 vb = y4[cbase + (sy * 4 + ky0 + 1) * 3 + sx];
            float acc = acc4(acc4(0.0f, va, wa), vb, wb);
            #pragma unroll
            for (int off = 16; off; off >>= 1)
                acc += __shfl_xor_sync(0xffffffffu, acc, off);
            float val = fmaxf(fmaf(acc + cb, scale, shift), 0.0f);
            best = fmaxf(best, val);
        }
    }
    if (lane == 0) g_c[f] = best;
}

// ---------------- Kernel C: gating MLP + argmax + chain build ----------------
__global__ void __launch_bounds__(32) gate_kernel(
    const float* __restrict__ w1, const float* __restrict__ b1,
    const float* __restrict__ w2, const float* __restrict__ b2,
    const float* __restrict__ w3, const float* __restrict__ b3)
{
    __shared__ float sc[32][65];
    const int tid = threadIdx.x;
    for (int i = tid; i < 2048; i += 32) sc[i >> 6][i & 63] = g_c[i];
    __syncwarp();

    float h1[32];
    #pragma unroll
    for (int j = 0; j < 32; j++) {
        float acc = b1[j];
        #pragma unroll 8
        for (int t = 0; t < 64; t++) acc = fmaf(sc[tid][t], w1[j * 64 + t], acc);
        h1[j] = fast_tanh(acc);
    }
    float h2[32];
    #pragma unroll
    for (int j = 0; j < 32; j++) {
        float acc = b2[j];
        #pragma unroll
        for (int t = 0; t < 32; t++) acc = fmaf(h1[t], w2[j * 32 + t], acc);
        h2[j] = fast_tanh(acc);
    }
    float bestv = -1e30f; int besti = 0;
    #pragma unroll
    for (int a = 0; a < 6; a++) {
        float acc = b3[a];
        #pragma unroll
        for (int t = 0; t < 32; t++) acc = fmaf(h2[t], w3[a * 32 + t], acc);
        if (acc > bestv) { bestv = acc; besti = a; }
    }
    g_p[tid] = besti;
    __syncwarp();

    if (tid == 0) {
        int cnt[6] = {0, 0, 0, 0, 0, 0};
        for (int b = 0; b < 32; b++) {
            int e = g_p[b];
            g_chain[e][cnt[e]++] = b;
        }
        for (int e = 0; e < 6; e++) g_chain_len[e] = cnt[e];
    }
}

// ---------------- Kernel D: per-expert LSTM chains + output head -------------
// 6 blocks, 32 threads. Lane k owns h[k], c[k], and gate rows {k,32+k,64+k,96+k}.
// Packed f32x2 dot: acc_g += (W[k][2j],W[k][2j+1]) * (h[2j],h[2j+1]).
// Double-buffered h in SMEM -> 1 syncwarp per step.
__global__ void __launch_bounds__(32) lstm_kernel(
    const float* __restrict__ wih,   // [6,128,1]
    const float* __restrict__ whh,   // [6,128,32]
    const float* __restrict__ bih,   // [6,128]
    const float* __restrict__ bhh,   // [6,128]
    const float* __restrict__ hn0,   // [6,32]
    const float* __restrict__ outw,  // [6,64]
    const float* __restrict__ outb,  // [6]
    float* __restrict__ out)         // [32,6]
{
    const int e = blockIdx.x;
    const int k = threadIdx.x;
    const int len = g_chain_len[e];
    if (len == 0) return;

    // recurrent weights, packed row-major float2 (natural layout)
    ull Wi[16], Wf[16], Wg[16], Wo[16];
    const ull* base = (const ull*)(whh + (long)e * 4096);
    #pragma unroll
    for (int j = 0; j < 16; j++) {
        Wi[j] = base[(0  + k) * 16 + j];
        Wf[j] = base[(32 + k) * 16 + j];
        Wg[j] = base[(64 + k) * 16 + j];
        Wo[j] = base[(96 + k) * 16 + j];
    }
    const float wii = wih[e * 128 + 0  + k];
    const float wif = wih[e * 128 + 32 + k];
    const float wig = wih[e * 128 + 64 + k];
    const float wio = wih[e * 128 + 96 + k];
    const float bi_ = bih[e * 128 + 0  + k] + bhh[e * 128 + 0  + k];
    const float bf_ = bih[e * 128 + 32 + k] + bhh[e * 128 + 32 + k];
    const float bg_ = bih[e * 128 + 64 + k] + bhh[e * 128 + 64 + k];
    const float bo_ = bih[e * 128 + 96 + k] + bhh[e * 128 + 96 + k];

    float h = hn0[e * 32 + k];

    __shared__ ull  sh2[2][16];      // double-buffered h (32 floats each)
    __shared__ float scx[64];
    __shared__ float sr[64];

    for (int s = 0; s < len; s++) {
        const int b = g_chain[e][s];
        scx[k]      = g_c[b * 64 + k];
        scx[k + 32] = g_c[b * 64 + 32 + k];
        ((float*)sh2[0])[k] = h;
        float cst = 0.0f;
        __syncwarp();

        #pragma unroll 1
        for (int t = 0; t < 64; t++) {
            const int cur = t & 1, nxt = cur ^ 1;
            const float xt = scx[t];
            // scalar x + bias parts (independent, issue early)
            const float xi = fmaf(wii, xt, bi_);
            const float xf = fmaf(wif, xt, bf_);
            const float xg = fmaf(wig, xt, bg_);
            const float xo = fmaf(wio, xt, bo_);

            ull aI0 = 0, aI1 = 0, aF0 = 0, aF1 = 0;
            ull aG0 = 0, aG1 = 0, aO0 = 0, aO1 = 0;
            #pragma unroll
            for (int j = 0; j < 16; j += 2) {
                const ull h0 = sh2[cur][j];
                const ull h1 = sh2[cur][j + 1];
                aF0 = fma2(Wf[j], h0, aF0);  aF1 = fma2(Wf[j + 1], h1, aF1);
                aI0 = fma2(Wi[j], h0, aI0);  aI1 = fma2(Wi[j + 1], h1, aI1);
                aG0 = fma2(Wg[j], h0, aG0);  aG1 = fma2(Wg[j + 1], h1, aG1);
                aO0 = fma2(Wo[j], h0, aO0);  aO1 = fma2(Wo[j + 1], h1, aO1);
            }
            aF0 = add2(aF0, aF1);
            aI0 = add2(aI0, aI1);
            aG0 = add2(aG0, aG1);
            aO0 = add2(aO0, aO1);
            const float af = lo2(aF0) + hi2(aF0) + xf;
            const float ai = lo2(aI0) + hi2(aI0) + xi;
            const float ag = lo2(aG0) + hi2(aG0) + xg;
            const float ao = lo2(aO0) + hi2(aO0) + xo;

            const float fg = sigap(af);
            const float ig = sigap(ai);
            const float gg = tanhap(ag);
            const float og = sigap(ao);
            cst = fmaf(fg, cst, ig * gg);
            h = og * tanhap(cst);

            ((float*)sh2[nxt])[k] = h;
            if (k == 31) sr[t] = h;
            __syncwarp();
        }

        if (k < 6) {
            float acc = outb[k];
            #pragma unroll 8
            for (int t = 0; t < 64; t++) acc = fmaf(sr[t], outw[k * 64 + t], acc);
            out[b * 6 + k] = acc;
        }
        __syncwarp();
    }
}

// ---------------- launch ----------------
extern "C" void kernel_launch(void* const* d_in, const int* in_sizes, int n_in,
                              void* d_out, int out_size)
{
    const float* x       = (const float*)d_in[0];
    const float* conv1_w = (const float*)d_in[1];
    const float* conv1_b = (const float*)d_in[2];
    const float* bn1_g   = (const float*)d_in[3];
    const float* bn1_b   = (const float*)d_in[4];
    const float* bn1_m   = (const float*)d_in[5];
    const float* bn1_v   = (const float*)d_in[6];
    const float* conv2_w = (const float*)d_in[7];
    const float* conv2_b = (const float*)d_in[8];
    const float* bn2_g   = (const float*)d_in[9];
    const float* bn2_b   = (const float*)d_in[10];
    const float* bn2_m   = (const float*)d_in[11];
    const float* bn2_v   = (const float*)d_in[12];
    const float* pre_w1  = (const float*)d_in[13];
    const float* pre_b1  = (const float*)d_in[14];
    const float* pre_w2  = (const float*)d_in[15];
    const float* pre_b2  = (const float*)d_in[16];
    const float* pre_w3  = (const float*)d_in[17];
    const float* pre_b3  = (const float*)d_in[18];
    const float* lstm_wih = (const float*)d_in[19];
    const float* lstm_whh = (const float*)d_in[20];
    const float* lstm_bih = (const float*)d_in[21];
    const float* lstm_bhh = (const float*)d_in[22];
    const float* hn0     = (const float*)d_in[23];
    const float* out_w   = (const float*)d_in[24];
    const float* out_b   = (const float*)d_in[25];
    float* out = (float*)d_out;

    dim3 gridA(FRAMES, 12);
    conv1_kernel<<<gridA, 96>>>(x, conv1_w, conv1_b, bn1_g, bn1_b, bn1_m, bn1_v);
    conv2_kernel<<<FRAMES / 8, 256>>>(conv2_w, conv2_b, bn2_g, bn2_b, bn2_m, bn2_v);
    gate_kernel<<<1, 32>>>(pre_w1, pre_b1, pre_w2, pre_b2, pre_w3, pre_b3);
    lstm_kernel<<<6, 32>>>(lstm_wih, lstm_whh, lstm_bih, lstm_bhh, hn0, out_w, out_b, out);
}

// round 3
// speedup vs baseline: 1.5226x; 1.1204x over previous
#include <cuda_runtime.h>
#include <math.h>

#define FRAMES 2048
#define BEPS 1e-5f

typedef unsigned long long ull;

// ---------------- scratch ----------------
__device__ __align__(16) float g_y1[FRAMES * 16 * 144];   // [2048,16,12,12]
__device__ float g_c[FRAMES];
__device__ int   g_p[32];
__device__ int   g_chain[6][32];
__device__ int   g_chain_len[6];

__device__ __forceinline__ float fast_tanh(float x) {
    return 1.0f - 2.0f / (1.0f + __expf(2.0f * x));
}
__device__ __forceinline__ float tanhap(float x) {
    float y;
    asm("tanh.approx.f32 %0, %1;" : "=f"(y) : "f"(x));
    return y;
}
__device__ __forceinline__ float sigap(float x) {
    return fmaf(0.5f, tanhap(0.5f * x), 0.5f);
}
__device__ __forceinline__ float acc4(float acc, float4 a, float4 b) {
    acc = fmaf(a.x, b.x, acc);
    acc = fmaf(a.y, b.y, acc);
    acc = fmaf(a.z, b.z, acc);
    acc = fmaf(a.w, b.w, acc);
    return acc;
}

// ---------------- Kernel A: conv1 + bias + BN + ReLU + 3x3/3 maxpool ----------
__global__ void __launch_bounds__(96) conv1_kernel(
    const float* __restrict__ x,
    const float* __restrict__ w,
    const float* __restrict__ bias,
    const float* __restrict__ bg, const float* __restrict__ bb,
    const float* __restrict__ bm, const float* __restrict__ bv)
{
    __shared__ float4 smem[1296];
    const int f  = blockIdx.x;
    const int py = blockIdx.y;
    const int tid = threadIdx.x;

    const float4* xin = (const float4*)x;
    const long base = (long)f * 15552 + (long)py * 432;
    for (int i = tid; i < 1296; i += 96) {
        int ic  = i / 432;
        int rem = i - ic * 432;
        smem[i] = xin[base + (long)ic * 5184 + rem];
    }
    __syncthreads();

    const int chp = tid & 7;
    const int px  = tid >> 3;
    const int ch0 = chp * 2, ch1 = ch0 + 1;

    float4 w0[12], w1[12];
    const float4* wf4 = (const float4*)w;
    #pragma unroll
    for (int i = 0; i < 12; i++) { w0[i] = wf4[ch0 * 12 + i]; w1[i] = wf4[ch1 * 12 + i]; }

    const float s0 = bg[ch0] * rsqrtf(bv[ch0] + BEPS);
    const float s1 = bg[ch1] * rsqrtf(bv[ch1] + BEPS);
    const float t0 = bb[ch0] - bm[ch0] * s0;
    const float t1 = bb[ch1] - bm[ch1] * s1;
    const float b0 = bias[ch0], b1 = bias[ch1];

    float m0 = -1e30f, m1 = -1e30f;
    #pragma unroll
    for (int sy = 0; sy < 3; sy++) {
        #pragma unroll
        for (int sx = 0; sx < 3; sx++) {
            float a0 = b0, a1 = b1;
            #pragma unroll
            for (int ic = 0; ic < 3; ic++) {
                #pragma unroll
                for (int ky = 0; ky < 4; ky++) {
                    float4 v = smem[(ic * 12 + sy * 4 + ky) * 36 + px * 3 + sx];
                    a0 = acc4(a0, v, w0[ic * 4 + ky]);
                    a1 = acc4(a1, v, w1[ic * 4 + ky]);
                }
            }
            m0 = fmaxf(m0, fmaxf(fmaf(a0, s0, t0), 0.0f));
            m1 = fmaxf(m1, fmaxf(fmaf(a1, s1, t1), 0.0f));
        }
    }
    g_y1[((f * 16 + ch0) * 12 + py) * 12 + px] = m0;
    g_y1[((f * 16 + ch1) * 12 + py) * 12 + px] = m1;
}

// ---------------- Kernel B: conv2 -> scalar per frame ------------------------
__global__ void __launch_bounds__(256) conv2_kernel(
    const float* __restrict__ w2, const float* __restrict__ b2p,
    const float* __restrict__ bg, const float* __restrict__ bb,
    const float* __restrict__ bm, const float* __restrict__ bv)
{
    const int f = blockIdx.x * 8 + (threadIdx.x >> 5);
    const int lane = threadIdx.x & 31;
    const int ch = lane & 15, half = lane >> 4;

    const float4* wf4 = (const float4*)w2;
    const float4 wa = wf4[ch * 4 + half * 2 + 0];
    const float4 wb = wf4[ch * 4 + half * 2 + 1];

    const float scale = bg[0] * rsqrtf(bv[0] + BEPS);
    const float shift = bb[0] - bm[0] * scale;
    const float cb = b2p[0];

    const float4* y4 = (const float4*)g_y1;
    const long cbase = ((long)f * 16 + ch) * 36;

    float best = -1e30f;
    #pragma unroll
    for (int sy = 0; sy < 3; sy++) {
        #pragma unroll
        for (int sx = 0; sx < 3; sx++) {
            int ky0 = half * 2;
            float4 va = y4[cbase + (sy * 4 + ky0) * 3 + sx];
            float4 vb = y4[cbase + (sy * 4 + ky0 + 1) * 3 + sx];
            float acc = acc4(acc4(0.0f, va, wa), vb, wb);
            #pragma unroll
            for (int off = 16; off; off >>= 1)
                acc += __shfl_xor_sync(0xffffffffu, acc, off);
            float val = fmaxf(fmaf(acc + cb, scale, shift), 0.0f);
            best = fmaxf(best, val);
        }
    }
    if (lane == 0) g_c[f] = best;
}

// ---------------- Kernel C: gating MLP + argmax + chain build ----------------
__global__ void __launch_bounds__(32) gate_kernel(
    const float* __restrict__ w1, const float* __restrict__ b1,
    const float* __restrict__ w2, const float* __restrict__ b2,
    const float* __restrict__ w3, const float* __restrict__ b3)
{
    __shared__ float sc[32][65];
    const int tid = threadIdx.x;
    for (int i = tid; i < 2048; i += 32) sc[i >> 6][i & 63] = g_c[i];
    __syncwarp();

    float h1[32];
    #pragma unroll
    for (int j = 0; j < 32; j++) {
        float acc = b1[j];
        #pragma unroll 8
        for (int t = 0; t < 64; t++) acc = fmaf(sc[tid][t], w1[j * 64 + t], acc);
        h1[j] = fast_tanh(acc);
    }
    float h2[32];
    #pragma unroll
    for (int j = 0; j < 32; j++) {
        float acc = b2[j];
        #pragma unroll
        for (int t = 0; t < 32; t++) acc = fmaf(h1[t], w2[j * 32 + t], acc);
        h2[j] = fast_tanh(acc);
    }
    float bestv = -1e30f; int besti = 0;
    #pragma unroll
    for (int a = 0; a < 6; a++) {
        float acc = b3[a];
        #pragma unroll
        for (int t = 0; t < 32; t++) acc = fmaf(h2[t], w3[a * 32 + t], acc);
        if (acc > bestv) { bestv = acc; besti = a; }
    }
    g_p[tid] = besti;
    __syncwarp();

    if (tid == 0) {
        int cnt[6] = {0, 0, 0, 0, 0, 0};
        for (int b = 0; b < 32; b++) {
            int e = g_p[b];
            g_chain[e][cnt[e]++] = b;
        }
        for (int e = 0; e < 6; e++) g_chain_len[e] = cnt[e];
    }
}

// ---------------- Kernel D: 4-warp per-expert LSTM + output head -------------
// 6 blocks x 128 threads. Warp w computes gate w (0=i,1=f,2=g,3=o) for all 32
// hidden units; lane k owns row 32w+k of whh. h and cst are kept REDUNDANTLY
// in registers in all 4 warps (bitwise identical), so only act values cross
// warps -> exactly one __syncthreads per timestep (double-buffered act).
__global__ void __launch_bounds__(128) lstm_kernel(
    const float* __restrict__ wih,   // [6,128,1]
    const float* __restrict__ whh,   // [6,128,32]
    const float* __restrict__ bih,   // [6,128]
    const float* __restrict__ bhh,   // [6,128]
    const float* __restrict__ hn0,   // [6,32]
    const float* __restrict__ outw,  // [6,64]
    const float* __restrict__ outb,  // [6]
    float* __restrict__ out)         // [32,6]
{
    const int e = blockIdx.x;
    const int tid = threadIdx.x;
    const int w = tid >> 5;          // gate index
    const int k = tid & 31;          // hidden unit
    const int len = g_chain_len[e];
    if (len == 0) return;

    const int row = 32 * w + k;
    float W[32];
    {
        const float4* wr = (const float4*)(whh + (long)e * 4096 + (long)row * 32);
        #pragma unroll
        for (int j = 0; j < 8; j++) {
            float4 v = wr[j];
            W[4 * j + 0] = v.x; W[4 * j + 1] = v.y;
            W[4 * j + 2] = v.z; W[4 * j + 3] = v.w;
        }
    }
    const float wx   = wih[e * 128 + row];
    const float bsum = bih[e * 128 + row] + bhh[e * 128 + row];
    const bool  isg  = (w == 2);

    float h = hn0[e * 32 + k];       // redundant copy in every warp

    __shared__ float4 actb[2][32];   // [buf][k] = (i,f,g,o)
    __shared__ float  scx[64];
    __shared__ float  sr[64];

    for (int s = 0; s < len; s++) {
        const int b = g_chain[e][s];
        if (w == 0) {
            scx[k]      = g_c[b * 64 + k];
            scx[k + 32] = g_c[b * 64 + 32 + k];
        }
        float cst = 0.0f;
        __syncthreads();

        #pragma unroll 2
        for (int t = 0; t < 64; t++) {
            // ---- gate phase: a = bsum + wx*x_t + W . h  (h via shuffles) ----
            const float xt = scx[t];
            float a = fmaf(wx, xt, bsum);
            float a0 = 0.0f, a1 = 0.0f, a2 = 0.0f, a3 = 0.0f;
            #pragma unroll
            for (int m = 0; m < 8; m++) {
                float h0 = __shfl_sync(0xffffffffu, h, 4 * m + 0);
                float h1 = __shfl_sync(0xffffffffu, h, 4 * m + 1);
                float h2 = __shfl_sync(0xffffffffu, h, 4 * m + 2);
                float h3 = __shfl_sync(0xffffffffu, h, 4 * m + 3);
                a0 = fmaf(W[4 * m + 0], h0, a0);
                a1 = fmaf(W[4 * m + 1], h1, a1);
                a2 = fmaf(W[4 * m + 2], h2, a2);
                a3 = fmaf(W[4 * m + 3], h3, a3);
            }
            a += (a0 + a1) + (a2 + a3);
            const float act = isg ? tanhap(a) : sigap(a);
            ((float*)(&actb[t & 1][k]))[w] = act;
            __syncthreads();

            // ---- elementwise phase (redundant in all warps) ----
            const float4 g4 = actb[t & 1][k];
            cst = fmaf(g4.y, cst, g4.x * g4.z);
            h = g4.w * tanhap(cst);
            if (w == 0 && k == 31) sr[t] = h;
        }

        // ---- output head (warp 0 only; sr written by its own lane 31) ----
        if (w == 0) {
            __syncwarp();
            if (k < 6) {
                float acc = outb[k];
                #pragma unroll 8
                for (int t = 0; t < 64; t++) acc = fmaf(sr[t], outw[k * 64 + t], acc);
                out[b * 6 + k] = acc;
            }
        }
    }
}

// ---------------- launch ----------------
extern "C" void kernel_launch(void* const* d_in, const int* in_sizes, int n_in,
                              void* d_out, int out_size)
{
    const float* x       = (const float*)d_in[0];
    const float* conv1_w = (const float*)d_in[1];
    const float* conv1_b = (const float*)d_in[2];
    const float* bn1_g   = (const float*)d_in[3];
    const float* bn1_b   = (const float*)d_in[4];
    const float* bn1_m   = (const float*)d_in[5];
    const float* bn1_v   = (const float*)d_in[6];
    const float* conv2_w = (const float*)d_in[7];
    const float* conv2_b = (const float*)d_in[8];
    const float* bn2_g   = (const float*)d_in[9];
    const float* bn2_b   = (const float*)d_in[10];
    const float* bn2_m   = (const float*)d_in[11];
    const float* bn2_v   = (const float*)d_in[12];
    const float* pre_w1  = (const float*)d_in[13];
    const float* pre_b1  = (const float*)d_in[14];
    const float* pre_w2  = (const float*)d_in[15];
    const float* pre_b2  = (const float*)d_in[16];
    const float* pre_w3  = (const float*)d_in[17];
    const float* pre_b3  = (const float*)d_in[18];
    const float* lstm_wih = (const float*)d_in[19];
    const float* lstm_whh = (const float*)d_in[20];
    const float* lstm_bih = (const float*)d_in[21];
    const float* lstm_bhh = (const float*)d_in[22];
    const float* hn0     = (const float*)d_in[23];
    const float* out_w   = (const float*)d_in[24];
    const float* out_b   = (const float*)d_in[25];
    float* out = (float*)d_out;

    dim3 gridA(FRAMES, 12);
    conv1_kernel<<<gridA, 96>>>(x, conv1_w, conv1_b, bn1_g, bn1_b, bn1_m, bn1_v);
    conv2_kernel<<<FRAMES / 8, 256>>>(conv2_w, conv2_b, bn2_g, bn2_b, bn2_m, bn2_v);
    gate_kernel<<<1, 32>>>(pre_w1, pre_b1, pre_w2, pre_b2, pre_w3, pre_b3);
    lstm_kernel<<<6, 128>>>(lstm_wih, lstm_whh, lstm_bih, lstm_bhh, hn0, out_w, out_b, out);
}

// round 4
// speedup vs baseline: 1.5725x; 1.0327x over previous
#include <cuda_runtime.h>
#include <math.h>

#define FRAMES 2048
#define BEPS 1e-5f

typedef unsigned long long ull;

// ---------------- scratch ----------------
__device__ __align__(16) float g_y1[FRAMES * 16 * 144];   // [2048,16,12,12]
__device__ float g_c[FRAMES];
__device__ int   g_p[32];
__device__ int   g_chain[6][32];
__device__ int   g_chain_len[6];

__device__ __forceinline__ float fast_tanh(float x) {
    return 1.0f - 2.0f / (1.0f + __expf(2.0f * x));
}
__device__ __forceinline__ float tanhap(float x) {
    float y;
    asm("tanh.approx.f32 %0, %1;" : "=f"(y) : "f"(x));
    return y;
}
__device__ __forceinline__ float sigap(float x) {
    return fmaf(0.5f, tanhap(0.5f * x), 0.5f);
}
__device__ __forceinline__ ull fma2(ull a, ull b, ull c) {
    ull d;
    asm("fma.rn.f32x2 %0, %1, %2, %3;" : "=l"(d) : "l"(a), "l"(b), "l"(c));
    return d;
}
__device__ __forceinline__ ull add2(ull a, ull b) {
    ull d;
    asm("add.rn.f32x2 %0, %1, %2;" : "=l"(d) : "l"(a), "l"(b));
    return d;
}
__device__ __forceinline__ float lo2(ull a) { return __uint_as_float((unsigned)(a & 0xffffffffu)); }
__device__ __forceinline__ float hi2(ull a) { return __uint_as_float((unsigned)(a >> 32)); }
__device__ __forceinline__ float acc4(float acc, float4 a, float4 b) {
    acc = fmaf(a.x, b.x, acc);
    acc = fmaf(a.y, b.y, acc);
    acc = fmaf(a.z, b.z, acc);
    acc = fmaf(a.w, b.w, acc);
    return acc;
}

// ---------------- Kernel A: conv1 + bias + BN + ReLU + 3x3/3 maxpool ----------
// grid (2048,12), 192 threads: thread = (px 0..11, ch 0..15), one channel each.
// Packed f32x2 accumulation over the K dimension (input elems pair naturally).
__global__ void __launch_bounds__(192) conv1_kernel(
    const float* __restrict__ x,
    const float* __restrict__ w,        // [16,3,4,4] = 24 f32x2 pairs per ch
    const float* __restrict__ bias,
    const float* __restrict__ bg, const float* __restrict__ bb,
    const float* __restrict__ bm, const float* __restrict__ bv)
{
    __shared__ float4 smem[1296];       // 3 * 12 * 36 float4
    const int f  = blockIdx.x;
    const int py = blockIdx.y;
    const int tid = threadIdx.x;

    const float4* xin = (const float4*)x;
    const long base = (long)f * 15552 + (long)py * 432;
    for (int i = tid; i < 1296; i += 192) {
        int ic  = i / 432;
        int rem = i - ic * 432;
        smem[i] = xin[base + (long)ic * 5184 + rem];
    }
    __syncthreads();

    const int ch = tid & 15;
    const int px = tid >> 4;            // 0..11

    // weights for this channel: 24 packed pairs
    ull wp[24];
    {
        const ull* wsrc = (const ull*)(w + ch * 48);
        #pragma unroll
        for (int j = 0; j < 24; j++) wp[j] = wsrc[j];
    }
    const float scale = bg[ch] * rsqrtf(bv[ch] + BEPS);
    const float shift = bb[ch] - bm[ch] * scale;
    const float cb = bias[ch];

    float m = -1e30f;
    #pragma unroll
    for (int sy = 0; sy < 3; sy++) {
        #pragma unroll
        for (int sx = 0; sx < 3; sx++) {
            ull A = 0, B = 0;           // two packed accumulator chains
            #pragma unroll
            for (int ic = 0; ic < 3; ic++) {
                #pragma unroll
                for (int ky = 0; ky < 4; ky++) {
                    const ulonglong2 v = *(const ulonglong2*)
                        &smem[(ic * 12 + sy * 4 + ky) * 36 + px * 3 + sx];
                    const int wi = (ic * 4 + ky) * 2;
                    A = fma2(v.x, wp[wi], A);
                    B = fma2(v.y, wp[wi + 1], B);
                }
            }
            const ull S = add2(A, B);
            const float a = lo2(S) + hi2(S) + cb;
            m = fmaxf(m, fmaxf(fmaf(a, scale, shift), 0.0f));
        }
    }
    g_y1[((f * 16 + ch) * 12 + py) * 12 + px] = m;
}

// ---------------- Kernel B: conv2 -> scalar per frame ------------------------
__global__ void __launch_bounds__(256) conv2_kernel(
    const float* __restrict__ w2, const float* __restrict__ b2p,
    const float* __restrict__ bg, const float* __restrict__ bb,
    const float* __restrict__ bm, const float* __restrict__ bv)
{
    const int f = blockIdx.x * 8 + (threadIdx.x >> 5);
    const int lane = threadIdx.x & 31;
    const int ch = lane & 15, half = lane >> 4;

    const float4* wf4 = (const float4*)w2;
    const float4 wa = wf4[ch * 4 + half * 2 + 0];
    const float4 wb = wf4[ch * 4 + half * 2 + 1];

    const float scale = bg[0] * rsqrtf(bv[0] + BEPS);
    const float shift = bb[0] - bm[0] * scale;
    const float cb = b2p[0];

    const float4* y4 = (const float4*)g_y1;
    const long cbase = ((long)f * 16 + ch) * 36;

    float best = -1e30f;
    #pragma unroll
    for (int sy = 0; sy < 3; sy++) {
        #pragma unroll
        for (int sx = 0; sx < 3; sx++) {
            int ky0 = half * 2;
            float4 va = y4[cbase + (sy * 4 + ky0) * 3 + sx];
            float4 vb = y4[cbase + (sy * 4 + ky0 + 1) * 3 + sx];
            float acc = acc4(acc4(0.0f, va, wa), vb, wb);
            #pragma unroll
            for (int off = 16; off; off >>= 1)
                acc += __shfl_xor_sync(0xffffffffu, acc, off);
            float val = fmaxf(fmaf(acc + cb, scale, shift), 0.0f);
            best = fmaxf(best, val);
        }
    }
    if (lane == 0) g_c[f] = best;
}

// ---------------- Kernel C: gating MLP + argmax + chain build ----------------
// 1024 threads: thread = (sample s = tid>>5, unit j = tid&31).
__global__ void __launch_bounds__(1024) gate_kernel(
    const float* __restrict__ w1, const float* __restrict__ b1,
    const float* __restrict__ w2, const float* __restrict__ b2,
    const float* __restrict__ w3, const float* __restrict__ b3)
{
    __shared__ float sc[32][65];
    __shared__ float sh1[32][33];
    __shared__ float sh2[32][33];
    __shared__ float sw1[2048];
    __shared__ float sw2[1024];
    const int tid = threadIdx.x;
    const int s = tid >> 5, j = tid & 31;

    for (int i = tid; i < 2048; i += 1024) {
        sc[i >> 6][i & 63] = g_c[i];
        sw1[i] = w1[i];
    }
    if (tid < 1024) sw2[tid] = w2[tid];
    __syncthreads();

    {
        float acc = b1[j];
        #pragma unroll 8
        for (int t = 0; t < 64; t++) acc = fmaf(sc[s][t], sw1[j * 64 + t], acc);
        sh1[s][j] = fast_tanh(acc);
    }
    __syncthreads();
    {
        float acc = b2[j];
        #pragma unroll
        for (int t = 0; t < 32; t++) acc = fmaf(sh1[s][t], sw2[j * 32 + t], acc);
        sh2[s][j] = fast_tanh(acc);
    }
    __syncthreads();

    if (tid < 32) {
        float bestv = -1e30f; int besti = 0;
        #pragma unroll
        for (int a = 0; a < 6; a++) {
            float acc = b3[a];
            #pragma unroll
            for (int t = 0; t < 32; t++) acc = fmaf(sh2[tid][t], w3[a * 32 + t], acc);
            if (acc > bestv) { bestv = acc; besti = a; }
        }
        g_p[tid] = besti;
    }
    __syncthreads();

    if (tid == 0) {
        int cnt[6] = {0, 0, 0, 0, 0, 0};
        for (int b = 0; b < 32; b++) {
            int e = g_p[b];
            g_chain[e][cnt[e]++] = b;
        }
        for (int e = 0; e < 6; e++) g_chain_len[e] = cnt[e];
    }
}

// ---------------- Kernel D: 4-warp per-expert LSTM + output head -------------
__global__ void __launch_bounds__(128) lstm_kernel(
    const float* __restrict__ wih,
    const float* __restrict__ whh,
    const float* __restrict__ bih,
    const float* __restrict__ bhh,
    const float* __restrict__ hn0,
    const float* __restrict__ outw,
    const float* __restrict__ outb,
    float* __restrict__ out)
{
    const int e = blockIdx.x;
    const int tid = threadIdx.x;
    const int w = tid >> 5;
    const int k = tid & 31;
    const int len = g_chain_len[e];
    if (len == 0) return;

    const int row = 32 * w + k;
    float W[32];
    {
        const float4* wr = (const float4*)(whh + (long)e * 4096 + (long)row * 32);
        #pragma unroll
        for (int j = 0; j < 8; j++) {
            float4 v = wr[j];
            W[4 * j + 0] = v.x; W[4 * j + 1] = v.y;
            W[4 * j + 2] = v.z; W[4 * j + 3] = v.w;
        }
    }
    const float wx   = wih[e * 128 + row];
    const float bsum = bih[e * 128 + row] + bhh[e * 128 + row];
    const bool  isg  = (w == 2);

    float h = hn0[e * 32 + k];

    __shared__ float4 actb[2][32];
    __shared__ float  scx[64];
    __shared__ float  sr[64];

    for (int s = 0; s < len; s++) {
        const int b = g_chain[e][s];
        if (w == 0) {
            scx[k]      = g_c[b * 64 + k];
            scx[k + 32] = g_c[b * 64 + 32 + k];
        }
        float cst = 0.0f;
        __syncthreads();

        #pragma unroll 4
        for (int t = 0; t < 64; t++) {
            const float xt = scx[t];
            float a = fmaf(wx, xt, bsum);
            float a0 = 0.0f, a1 = 0.0f, a2 = 0.0f, a3 = 0.0f;
            #pragma unroll
            for (int m = 0; m < 8; m++) {
                float h0 = __shfl_sync(0xffffffffu, h, 4 * m + 0);
                float h1 = __shfl_sync(0xffffffffu, h, 4 * m + 1);
                float h2 = __shfl_sync(0xffffffffu, h, 4 * m + 2);
                float h3 = __shfl_sync(0xffffffffu, h, 4 * m + 3);
                a0 = fmaf(W[4 * m + 0], h0, a0);
                a1 = fmaf(W[4 * m + 1], h1, a1);
                a2 = fmaf(W[4 * m + 2], h2, a2);
                a3 = fmaf(W[4 * m + 3], h3, a3);
            }
            a += (a0 + a1) + (a2 + a3);
            const float act = isg ? tanhap(a) : sigap(a);
            ((float*)(&actb[t & 1][k]))[w] = act;
            __syncthreads();

            const float4 g4 = actb[t & 1][k];
            cst = fmaf(g4.y, cst, g4.x * g4.z);
            h = g4.w * tanhap(cst);
            if (w == 0 && k == 31) sr[t] = h;
        }

        if (w == 0) {
            __syncwarp();
            if (k < 6) {
                float acc = outb[k];
                #pragma unroll 8
                for (int t = 0; t < 64; t++) acc = fmaf(sr[t], outw[k * 64 + t], acc);
                out[b * 6 + k] = acc;
            }
        }
    }
}

// ---------------- launch ----------------
extern "C" void kernel_launch(void* const* d_in, const int* in_sizes, int n_in,
                              void* d_out, int out_size)
{
    const float* x       = (const float*)d_in[0];
    const float* conv1_w = (const float*)d_in[1];
    const float* conv1_b = (const float*)d_in[2];
    const float* bn1_g   = (const float*)d_in[3];
    const float* bn1_b   = (const float*)d_in[4];
    const float* bn1_m   = (const float*)d_in[5];
    const float* bn1_v   = (const float*)d_in[6];
    const float* conv2_w = (const float*)d_in[7];
    const float* conv2_b = (const float*)d_in[8];
    const float* bn2_g   = (const float*)d_in[9];
    const float* bn2_b   = (const float*)d_in[10];
    const float* bn2_m   = (const float*)d_in[11];
    const float* bn2_v   = (const float*)d_in[12];
    const float* pre_w1  = (const float*)d_in[13];
    const float* pre_b1  = (const float*)d_in[14];
    const float* pre_w2  = (const float*)d_in[15];
    const float* pre_b2  = (const float*)d_in[16];
    const float* pre_w3  = (const float*)d_in[17];
    const float* pre_b3  = (const float*)d_in[18];
    const float* lstm_wih = (const float*)d_in[19];
    const float* lstm_whh = (const float*)d_in[20];
    const float* lstm_bih = (const float*)d_in[21];
    const float* lstm_bhh = (const float*)d_in[22];
    const float* hn0     = (const float*)d_in[23];
    const float* out_w   = (const float*)d_in[24];
    const float* out_b   = (const float*)d_in[25];
    float* out = (float*)d_out;

    dim3 gridA(FRAMES, 12);
    conv1_kernel<<<gridA, 192>>>(x, conv1_w, conv1_b, bn1_g, bn1_b, bn1_m, bn1_v);
    conv2_kernel<<<FRAMES / 8, 256>>>(conv2_w, conv2_b, bn2_g, bn2_b, bn2_m, bn2_v);
    gate_kernel<<<1, 1024>>>(pre_w1, pre_b1, pre_w2, pre_b2, pre_w3, pre_b3);
    lstm_kernel<<<6, 128>>>(lstm_wih, lstm_whh, lstm_bih, lstm_bhh, hn0, out_w, out_b, out);
}